// round 12
// baseline (speedup 1.0000x reference)
#include <cuda_runtime.h>

#define NBLK 128
#define NTHR 512
#define Bc   64
#define Tc   1024
#define Hc   256
#define DINc 12
#define NCc  17

typedef unsigned long long u64;

// ---------------- static device scratch (no allocations allowed) ----------------
__device__ float g_xT[Tc * DINc * Bc];           // x transposed [t][k][b]
__device__ float g_out0[(size_t)Tc * 512 * Bc];  // layer-0 out  [t][k][b]  (128 MB)
__device__ float g_xp[(size_t)NBLK * Tc * 16 * Bc]; // xproj+bias per block [t][r16][b64] (512 MB)
__device__ float g_hbuf[2 * 2 * Hc * Bc];        // [dir][parity][j][b]
__device__ float g_pooled[512 * Bc];             // [k][b]
// Barrier state: per-dir (64 blocks each) + full (128 blocks). Padded apart.
__device__ unsigned g_cnt_d[2 * 32];             // counters, self-reset each round
__device__ volatile unsigned g_sn_d[2 * 32];     // completed-round counts (monotone)
__device__ unsigned g_cnt_f;
__device__ volatile unsigned g_sn_f;

// ---------------- helpers ----------------
__device__ __forceinline__ u64 pk2(float v) {
    u64 r; asm("mov.b64 %0, {%1, %2};" : "=l"(r) : "f"(v), "f"(v)); return r;
}
__device__ __forceinline__ void fma2(u64 &a, u64 x, u64 w) {
    asm("fma.rn.f32x2 %0, %1, %2, %0;" : "+l"(a) : "l"(x), "l"(w));
}
__device__ __forceinline__ float2 up2(u64 v) {
    float2 f; asm("mov.b64 {%0, %1}, %2;" : "=f"(f.x), "=f"(f.y) : "l"(v)); return f;
}
__device__ __forceinline__ float sigm_(float x) { return 1.0f / (1.0f + __expf(-x)); }
__device__ __forceinline__ float tanh_(float x) {
    float e = __expf(-2.0f * fabsf(x));
    float r = (1.0f - e) / (1.0f + e);
    return x >= 0.f ? r : -r;
}

// Fused sense-style barrier (proven round-7/9/10 algorithm, unchanged).
__device__ __forceinline__ void gbar(unsigned *cnt, volatile unsigned *gs,
                                     unsigned &ls, unsigned n) {
    __syncthreads();
    unsigned tgt = ls + 1u;
    if (threadIdx.x == 0) {
        __threadfence();
        if (atomicAdd(cnt, 1u) == n - 1u) {
            *cnt = 0u;
            __threadfence();
            *gs = tgt;
        } else {
            while ((int)(*gs - tgt) < 0) { }
        }
    }
    ls = tgt;
    __syncthreads();
}

// acc[rr*2 + j] += A_j * w_rr   (4 rows x 4 batches, batches as 2 u64 pairs)
__device__ __forceinline__ void mac8(u64 *acc, float4 wv, ulonglong2 A) {
    u64 w0 = pk2(wv.x), w1 = pk2(wv.y), w2 = pk2(wv.z), w3 = pk2(wv.w);
    fma2(acc[0], A.x, w0); fma2(acc[1], A.y, w0);
    fma2(acc[2], A.x, w1); fma2(acc[3], A.y, w1);
    fma2(acc[4], A.x, w2); fma2(acc[5], A.y, w2);
    fma2(acc[6], A.x, w3); fma2(acc[7], A.y, w3);
}

// ---------------- barrier-free x-projection precompute ----------------
// xp[t][r16][b64] = bias[r] + sum_{k<KLIN} ws[k][r] * in[t][k][b]
// Same 8-way k-split + smem reduction as the recurrence loop, looped over t.
template <int KLIN>
__device__ void precompute_xp(
    int tid, const float *__restrict__ inbase, const float *ws,
    u64 *red, const float *bias, float *__restrict__ xpslab)
{
    const int lane = tid & 31;
    const int ks   = (tid >> 5) & 7;
    const int bh   = tid >> 8;
    const int rg   = lane >> 3;
    const int bg   = lane & 7;
    const int boff = bh * 32 + bg * 4;
    // gather-side constants (output r, batch-pair bp per thread)
    const int r = tid >> 5, bp = tid & 31;
    const int bh2 = bp >> 4, p = bp & 15, bg2 = p >> 1, jj = p & 1;
    const int lane2 = (r >> 2) * 8 + bg2;
    const int ii = (r & 3) * 2 + jj;

    for (int t = 0; t < Tc; t++) {
        u64 acc[8];
        #pragma unroll
        for (int i = 0; i < 8; i++) acc[i] = 0ull;

        const float *xsrc = inbase + (size_t)t * KLIN * Bc;
        #pragma unroll 4
        for (int k = ks; k < KLIN; k += 8) {
            float4 wv = *(const float4 *)(ws + k * 16 + rg * 4);
            ulonglong2 A = __ldcg((const ulonglong2 *)(xsrc + k * Bc + boff));
            mac8(acc, wv, A);
        }

        __syncthreads();   // red free (previous t's gather done)
        #pragma unroll
        for (int i = 0; i < 8; i++) red[tid * 9 + i] = acc[i];
        __syncthreads();

        float2 sc = make_float2(bias[r], bias[r]);
        #pragma unroll
        for (int q = 0; q < 8; q++) {
            float2 v = up2(red[(((bh2 * 8 + q) * 32) + lane2) * 9 + ii]);
            sc.x += v.x; sc.y += v.y;
        }
        __stcg((float2 *)(xpslab + (size_t)t * 1024 + r * 64 + bp * 2), sc);
    }
}

// ---------------- recurrence loop: h-part only (x hoisted into xp) ----------------
template <bool PH1>
__device__ void run_phase(
    int dir, int ub, int tid, int klin,
    const float *__restrict__ inbase,
    const float *__restrict__ w_ih, const float *__restrict__ w_hh,
    const float *__restrict__ b_ih, const float *__restrict__ b_hh,
    const float *__restrict__ xpslab,
    float *ws, u64 *red, float *gates, float *cst, float *bias,
    unsigned &sd, unsigned &sf, float &pool)
{
    const int klen = klin + Hc;

    // Stage weights transposed: ws[k*16 + r]  (x rows for precompute, h rows for loop)
    for (int idx = tid; idx < 16 * klen; idx += NTHR) {
        int r = idx / klen, k = idx - r * klen;
        int grow = (r >> 2) * Hc + ub + (r & 3);       // gate*256 + unit
        float v = (k < klin) ? w_ih[(size_t)(dir * 1024 + grow) * klin + k]
                             : w_hh[(size_t)(dir * 1024 + grow) * Hc + (k - klin)];
        ws[k * 16 + r] = v;
    }
    if (tid < 16) {
        int grow = (tid >> 2) * Hc + ub + (tid & 3);
        bias[tid] = b_ih[dir * 1024 + grow] + b_hh[dir * 1024 + grow];
    }
    // Zero cell state + this block's slice of h parity-0 buffer
    if (tid < 4 * Bc) {
        cst[tid] = 0.f;
        int u = tid >> 6, b = tid & 63;
        g_hbuf[((dir * 2 + 0) * Hc + ub + u) * Bc + b] = 0.f;
    }
    __threadfence();
    gbar(&g_cnt_f, &g_sn_f, sf, NBLK);   // full: prev phase outputs + inits visible

    // ---- barrier-free precompute of this block's xp (reads only own inputs) ----
    if (klin == DINc) precompute_xp<DINc>(tid, inbase, ws, red, bias, (float *)xpslab);
    else              precompute_xp<512 >(tid, inbase, ws, red, bias, (float *)xpslab);

    const int lane = tid & 31;
    const int ks   = (tid >> 5) & 7;
    const int bh   = tid >> 8;
    const int rg   = lane >> 3;
    const int bg   = lane & 7;
    const int boff = bh * 32 + bg * 4;
    const float *wsh = ws + klin * 16;     // h-rows of the weight tile
    // gather-side constants
    const int r = tid >> 5, bp = tid & 31;
    const int bh2 = bp >> 4, p = bp & 15, bg2 = p >> 1, jj = p & 1;
    const int lane2 = (r >> 2) * 8 + bg2;
    const int ii = (r & 3) * 2 + jj;

    for (int s = 0; s < Tc; s++) {
        const int t = dir ? (Tc - 1 - s) : s;

        u64 acc[8];
        #pragma unroll
        for (int i = 0; i < 8; i++) acc[i] = 0ull;

        // ---- h-part (h(s-1) globally visible: barrier at end of step s-1) ----
        const float *hsrc = g_hbuf + (dir * 2 + (s & 1)) * Hc * Bc;
        #pragma unroll 4
        for (int k = ks; k < Hc; k += 8) {
            float4 wv = *(const float4 *)(wsh + k * 16 + rg * 4);
            ulonglong2 A = __ldcg((const ulonglong2 *)(hsrc + k * Bc + boff));
            mac8(acc, wv, A);
        }

        // ---- 8-way k-segment reduction + xp add ----
        #pragma unroll
        for (int i = 0; i < 8; i++) red[tid * 9 + i] = acc[i];
        __syncthreads();
        {
            float2 sc = __ldcg((const float2 *)(xpslab + (size_t)t * 1024 + r * 64 + bp * 2));
            #pragma unroll
            for (int q = 0; q < 8; q++) {
                float2 v = up2(red[(((bh2 * 8 + q) * 32) + lane2) * 9 + ii]);
                sc.x += v.x; sc.y += v.y;
            }
            *(float2 *)(gates + r * Bc + bp * 2) = sc;
        }
        __syncthreads();

        // ---- pointwise LSTM cell update: thread (unit, batch), tid<256 ----
        if (tid < 256) {
            int uu = tid >> 6, bb = tid & 63;
            float gi = gates[(0 * 4 + uu) * Bc + bb];
            float gf = gates[(1 * 4 + uu) * Bc + bb];
            float gg = gates[(2 * 4 + uu) * Bc + bb];
            float go = gates[(3 * 4 + uu) * Bc + bb];
            float cc = cst[uu * Bc + bb];
            cc = sigm_(gf) * cc + sigm_(gi) * tanh_(gg);
            float hh = sigm_(go) * tanh_(cc);
            cst[uu * Bc + bb] = cc;
            g_hbuf[((dir * 2 + ((s & 1) ^ 1)) * Hc + ub + uu) * Bc + bb] = hh;
            if (!PH1) g_out0[((size_t)t * 512 + dir * Hc + ub + uu) * Bc + bb] = hh;
            else      pool += hh;
        }
        __threadfence();   // release own h/out0 stores
        gbar(&g_cnt_d[dir * 32], &g_sn_d[dir * 32], sd, 64);   // per-dir step barrier
    }
}

// ---------------- main persistent kernel ----------------
__global__ void __launch_bounds__(NTHR, 1) bilstm_kernel(
    const float *__restrict__ x,
    const float *__restrict__ w_ih0, const float *__restrict__ w_hh0,
    const float *__restrict__ b_ih0, const float *__restrict__ b_hh0,
    const float *__restrict__ w_ih1, const float *__restrict__ w_hh1,
    const float *__restrict__ b_ih1, const float *__restrict__ b_hh1,
    const float *__restrict__ fc_w, const float *__restrict__ fc_b,
    float *__restrict__ out)
{
    extern __shared__ float sm[];
    float *ws    = sm;                         // 12288 floats (48KB)
    u64   *red   = (u64 *)(sm + 12288);        // 4608 u64 (36KB, stride-9/thread)
    float *gates = sm + 12288 + 9216;          // 1024 floats
    float *cst   = gates + 1024;               // 256 floats
    float *bias  = cst + 256;                  // 16 floats

    const int tid = threadIdx.x;
    const int gb  = blockIdx.x;
    const int dir = gb >> 6;
    const int ub  = (gb & 63) * 4;
    float *xpslab = g_xp + (size_t)gb * Tc * 16 * Bc;

    // Monotone barrier round mirrors (persist across graph replays)
    unsigned sd = g_sn_d[dir * 32];
    unsigned sf = g_sn_f;

    // transpose x -> g_xT[t][k][b]
    for (int i = gb * NTHR + tid; i < Tc * DINc * Bc; i += NBLK * NTHR) {
        int b = i & 63;
        int j = i >> 6;
        int k = j % DINc;
        int t = j / DINc;
        g_xT[i] = x[((size_t)b * Tc + t) * DINc + k];
    }
    __threadfence();

    float pool = 0.f;
    run_phase<false>(dir, ub, tid, DINc, g_xT,  w_ih0, w_hh0, b_ih0, b_hh0, xpslab,
                     ws, red, gates, cst, bias, sd, sf, pool);
    run_phase<true >(dir, ub, tid, 512,  g_out0, w_ih1, w_hh1, b_ih1, b_hh1, xpslab,
                     ws, red, gates, cst, bias, sd, sf, pool);

    // mean-pool write (matches pointwise ownership)
    if (tid < 256) {
        int u = tid >> 6, b = tid & 63;
        g_pooled[(dir * Hc + ub + u) * Bc + b] = pool * (1.0f / (float)Tc);
    }
    __threadfence();
    gbar(&g_cnt_f, &g_sn_f, sf, NBLK);

    // final FC on block 0 (64x17 dots of length 512, k-split 8 ways)
    if (gb == 0) {
        for (int i = tid; i < NCc * 512; i += NTHR) ws[i] = fc_w[i];
        __syncthreads();
        float *redf = (float *)red;
        int b = tid & 63, kq = tid >> 6;           // 8 segments of 64 k
        float part[NCc];
        #pragma unroll
        for (int c = 0; c < NCc; c++) part[c] = 0.f;
        for (int k = kq * 64; k < kq * 64 + 64; k++) {
            float pv = __ldcg(&g_pooled[k * Bc + b]);
            #pragma unroll
            for (int c = 0; c < NCc; c++) part[c] += pv * ws[c * 512 + k];
        }
        #pragma unroll
        for (int c = 0; c < NCc; c++) redf[(kq * NCc + c) * Bc + b] = part[c];
        __syncthreads();
        for (int o = tid; o < Bc * NCc; o += NTHR) {
            int c = o >> 6, b2 = o & 63;
            float s_ = fc_b[c];
            #pragma unroll
            for (int q = 0; q < 8; q++) s_ += redf[(q * NCc + c) * Bc + b2];
            out[b2 * NCc + c] = s_;
        }
    }
}

// ---------------- launch ----------------
extern "C" void kernel_launch(void *const *d_in, const int *in_sizes, int n_in,
                              void *d_out, int out_size)
{
    (void)in_sizes; (void)n_in; (void)out_size;
    const float *x     = (const float *)d_in[0];
    const float *w_ih0 = (const float *)d_in[1];
    const float *w_hh0 = (const float *)d_in[2];
    const float *b_ih0 = (const float *)d_in[3];
    const float *b_hh0 = (const float *)d_in[4];
    const float *w_ih1 = (const float *)d_in[5];
    const float *w_hh1 = (const float *)d_in[6];
    const float *b_ih1 = (const float *)d_in[7];
    const float *b_hh1 = (const float *)d_in[8];
    const float *fc_w  = (const float *)d_in[9];
    const float *fc_b  = (const float *)d_in[10];
    float *out = (float *)d_out;

    // 120KB dynamic smem (91KB used, padded): forces 1 block/SM so all 128
    // blocks are co-resident (required by the software global barriers).
    const int smem = 120 * 1024;
    cudaFuncSetAttribute(bilstm_kernel, cudaFuncAttributeMaxDynamicSharedMemorySize, smem);

    bilstm_kernel<<<NBLK, NTHR, smem>>>(x, w_ih0, w_hh0, b_ih0, b_hh0,
                                        w_ih1, w_hh1, b_ih1, b_hh1,
                                        fc_w, fc_b, out);
}

// round 13
// speedup vs baseline: 1.2495x; 1.2495x over previous
#include <cuda_runtime.h>

#define NBLK 128
#define NTHR 512
#define Bc   64
#define Tc   1024
#define Hc   256
#define DINc 12
#define NCc  17

typedef unsigned long long u64;

// ---------------- static device scratch (no allocations allowed) ----------------
__device__ float g_xT[Tc * DINc * Bc];           // x transposed [t][k][b]
__device__ float g_out0[(size_t)Tc * 512 * Bc];  // layer-0 out  [t][k][b]  (128 MB)
__device__ float g_hbuf[2 * 2 * Hc * Bc];        // [dir][parity][j][b]
__device__ float g_pooled[512 * Bc];             // [k][b]
// Barrier state: per-dir (64 blocks each) + full (128 blocks). Padded apart.
__device__ unsigned g_cnt_d[2 * 32];             // counters, self-reset each round
__device__ volatile unsigned g_sn_d[2 * 32];     // completed-round counts (monotone)
__device__ unsigned g_cnt_f;
__device__ volatile unsigned g_sn_f;

// ---------------- helpers ----------------
__device__ __forceinline__ u64 pk2(float v) {
    u64 r; asm("mov.b64 %0, {%1, %2};" : "=l"(r) : "f"(v), "f"(v)); return r;
}
__device__ __forceinline__ void fma2(u64 &a, u64 x, u64 w) {
    asm("fma.rn.f32x2 %0, %1, %2, %0;" : "+l"(a) : "l"(x), "l"(w));
}
__device__ __forceinline__ float sigm_(float x) { return 1.0f / (1.0f + __expf(-x)); }
__device__ __forceinline__ float tanh_(float x) {
    float e = __expf(-2.0f * fabsf(x));
    float r = (1.0f - e) / (1.0f + e);
    return x >= 0.f ? r : -r;
}

// CG-style split barrier on the proven flat self-resetting counter.
// bar_arrive: called by tid 0 ONLY, after __syncthreads() (release pattern:
// bar.sync orders the CTA's stores; the elected thread's fence extends to GPU
// scope — exactly the cooperative-groups grid.sync pattern).
__device__ __forceinline__ void bar_arrive(unsigned *cnt, volatile unsigned *gs,
                                           unsigned tgt, unsigned n) {
    __threadfence();
    if (atomicAdd(cnt, 1u) == n - 1u) {
        *cnt = 0u;
        __threadfence();
        *gs = tgt;
    }
}
__device__ __forceinline__ void bar_wait(volatile unsigned *gs, unsigned tgt) {
    if (threadIdx.x == 0) {
        while ((int)(*gs - tgt) < 0) { }
        __threadfence();   // acquire
    }
    __syncthreads();
}

// acc[rr*2 + j] += A_j * w_rr   (4 rows x 4 batches, batches as 2 u64 pairs)
__device__ __forceinline__ void mac8(u64 *acc, float4 wv, ulonglong2 A) {
    u64 w0 = pk2(wv.x), w1 = pk2(wv.y), w2 = pk2(wv.z), w3 = pk2(wv.w);
    fma2(acc[0], A.x, w0); fma2(acc[1], A.y, w0);
    fma2(acc[2], A.x, w1); fma2(acc[3], A.y, w1);
    fma2(acc[4], A.x, w2); fma2(acc[5], A.y, w2);
    fma2(acc[6], A.x, w3); fma2(acc[7], A.y, w3);
}

// x-part of one step: zero accs, accumulate the input-projection contribution.
template <int KLIN>
__device__ __forceinline__ void xpart(u64 *acc, const float *__restrict__ xsrc,
                                      const float *ws, int ks, int rg, int boff) {
    #pragma unroll
    for (int i = 0; i < 8; i++) acc[i] = 0ull;
    #pragma unroll 4
    for (int k = ks; k < KLIN; k += 8) {
        float4 wv = *(const float4 *)(ws + k * 16 + rg * 4);
        ulonglong2 A = __ldcg((const ulonglong2 *)(xsrc + k * Bc + boff));
        mac8(acc, wv, A);
    }
}

// ---------------- one bidirectional-LSTM phase (fused input projection) ----------------
// Block gb: dir = gb>>6, owns 4 hidden units ub..ub+3 (16 gate rows in shared,
// transposed). 16 warps = 8 k-segments x 2 batch-halves; per lane 4 rows x 4
// batches. Split barrier: arrive after pointwise, next step's x-part in the
// shadow, wait just before the h-part.
template <int KLIN, bool PH1>
__device__ void run_phase(
    int dir, int ub, int tid,
    const float *__restrict__ inbase,
    const float *__restrict__ w_ih, const float *__restrict__ w_hh,
    const float *__restrict__ b_ih, const float *__restrict__ b_hh,
    float *ws, u64 *red,
    unsigned &sd, unsigned &sf, float &pool)
{
    constexpr int KLEN = KLIN + Hc;

    // Stage weights transposed: ws[k*16 + r]  (coalesced global reads)
    for (int idx = tid; idx < 16 * KLEN; idx += NTHR) {
        int r = idx / KLEN, k = idx - r * KLEN;
        int grow = (r >> 2) * Hc + ub + (r & 3);       // gate*256 + unit
        float v = (k < KLIN) ? w_ih[(size_t)(dir * 1024 + grow) * KLIN + k]
                             : w_hh[(size_t)(dir * 1024 + grow) * Hc + (k - KLIN)];
        ws[k * 16 + r] = v;
    }

    // Consumer-side per-thread state: cell state + 4 gate biases in registers.
    const int uu = tid >> 6, bb = tid & 63;
    float creg = 0.f;
    float bs[4] = {0.f, 0.f, 0.f, 0.f};
    int cbase = 0;
    if (tid < 256) {
        #pragma unroll
        for (int g = 0; g < 4; g++) {
            int bi = dir * 1024 + g * Hc + ub + uu;
            bs[g] = b_ih[bi] + b_hh[bi];
        }
        __stcg(&g_hbuf[((dir * 2 + 0) * Hc + ub + uu) * Bc + bb], 0.f);
        int bh2 = bb >> 5, bg2 = (bb & 31) >> 2, jp = (bb & 3) >> 1, lh = bb & 1;
        cbase = (bh2 * 256 + bg2) * 18 + uu * 4 + jp * 2 + lh;
    }
    __syncthreads();
    ++sf;
    if (tid == 0) bar_arrive(&g_cnt_f, &g_sn_f, sf, NBLK);
    bar_wait(&g_sn_f, sf);   // prev phase outputs + inits visible chip-wide

    const int lane = tid & 31;
    const int ks   = (tid >> 5) & 7;     // k-segment (stride 8)
    const int bh   = tid >> 8;           // batch half (0/1)
    const int rg   = lane >> 3;          // gate (rows rg*4..rg*4+3)
    const int bg   = lane & 7;           // 4 batches at bh*32 + bg*4
    const int boff = bh * 32 + bg * 4;
    const float *wsh  = ws + KLIN * 16;  // h-rows of the weight tile
    const float *redf = (const float *)red;
    volatile unsigned *gsd = &g_sn_d[dir * 32];
    unsigned *cntd = &g_cnt_d[dir * 32];

    u64 acc[8];
    xpart<KLIN>(acc, inbase + (size_t)(dir ? Tc - 1 : 0) * KLIN * Bc, ws, ks, rg, boff);

    for (int s = 0;;) {
        if (s > 0) bar_wait(gsd, sd);    // h(s-1) now visible

        // ---- h-part ----
        const float *hsrc = g_hbuf + (dir * 2 + (s & 1)) * Hc * Bc;
        #pragma unroll 4
        for (int k = ks; k < Hc; k += 8) {
            float4 wv = *(const float4 *)(wsh + k * 16 + rg * 4);
            ulonglong2 A = __ldcg((const ulonglong2 *)(hsrc + k * Bc + boff));
            mac8(acc, wv, A);
        }

        // ---- publish partials; merged gather + pointwise (tid<256) ----
        #pragma unroll
        for (int i = 0; i < 8; i++) red[tid * 9 + i] = acc[i];
        __syncthreads();
        const int t = dir ? (Tc - 1 - s) : s;
        if (tid < 256) {
            float gv[4];
            #pragma unroll
            for (int g = 0; g < 4; g++) {
                float sacc = bs[g];
                #pragma unroll
                for (int q = 0; q < 8; q++)
                    sacc += redf[cbase + g * 144 + q * 576];
                gv[g] = sacc;
            }
            float cc = sigm_(gv[1]) * creg + sigm_(gv[0]) * tanh_(gv[2]);
            float hh = sigm_(gv[3]) * tanh_(cc);
            creg = cc;
            __stcg(&g_hbuf[((dir * 2 + ((s & 1) ^ 1)) * Hc + ub + uu) * Bc + bb], hh);
            if (!PH1) __stcg(&g_out0[((size_t)t * 512 + dir * Hc + ub + uu) * Bc + bb], hh);
            else      pool += hh;
        }
        __syncthreads();
        ++sd;
        if (tid == 0) bar_arrive(cntd, gsd, sd, 64);   // arrive; wait deferred

        if (++s == Tc) break;
        // ---- next step's x-part in the barrier shadow ----
        xpart<KLIN>(acc, inbase + (size_t)(dir ? Tc - 1 - s : s) * KLIN * Bc,
                    ws, ks, rg, boff);
    }
}

// ---------------- main persistent kernel ----------------
__global__ void __launch_bounds__(NTHR, 1) bilstm_kernel(
    const float *__restrict__ x,
    const float *__restrict__ w_ih0, const float *__restrict__ w_hh0,
    const float *__restrict__ b_ih0, const float *__restrict__ b_hh0,
    const float *__restrict__ w_ih1, const float *__restrict__ w_hh1,
    const float *__restrict__ b_ih1, const float *__restrict__ b_hh1,
    const float *__restrict__ fc_w, const float *__restrict__ fc_b,
    float *__restrict__ out)
{
    extern __shared__ float sm[];
    float *ws  = sm;                     // 12288 floats (48KB)
    u64   *red = (u64 *)(sm + 12288);    // 4608 u64 (36KB, stride-9/thread)

    const int tid = threadIdx.x;
    const int gb  = blockIdx.x;
    const int dir = gb >> 6;
    const int ub  = (gb & 63) * 4;

    // Monotone barrier round mirrors (persist across graph replays)
    unsigned sd = g_sn_d[dir * 32];
    unsigned sf = g_sn_f;

    // transpose x -> g_xT[t][k][b]
    for (int i = gb * NTHR + tid; i < Tc * DINc * Bc; i += NBLK * NTHR) {
        int b = i & 63;
        int j = i >> 6;
        int k = j % DINc;
        int t = j / DINc;
        g_xT[i] = x[((size_t)b * Tc + t) * DINc + k];
    }

    float pool = 0.f;
    run_phase<DINc, false>(dir, ub, tid, g_xT,  w_ih0, w_hh0, b_ih0, b_hh0,
                           ws, red, sd, sf, pool);
    run_phase<512,  true >(dir, ub, tid, g_out0, w_ih1, w_hh1, b_ih1, b_hh1,
                           ws, red, sd, sf, pool);

    // mean-pool write (matches pointwise ownership)
    if (tid < 256) {
        int u = tid >> 6, b = tid & 63;
        __stcg(&g_pooled[(dir * Hc + u * 1 + ub) * Bc + b], pool * (1.0f / (float)Tc));
    }
    __syncthreads();
    ++sf;
    if (tid == 0) bar_arrive(&g_cnt_f, &g_sn_f, sf, NBLK);

    // final FC on block 0 (64x17 dots of length 512, k-split 8 ways)
    if (gb == 0) {
        bar_wait(&g_sn_f, sf);
        for (int i = tid; i < NCc * 512; i += NTHR) ws[i] = fc_w[i];
        __syncthreads();
        float *redf = (float *)red;
        int b = tid & 63, kq = tid >> 6;           // 8 segments of 64 k
        float part[NCc];
        #pragma unroll
        for (int c = 0; c < NCc; c++) part[c] = 0.f;
        for (int k = kq * 64; k < kq * 64 + 64; k++) {
            float pv = __ldcg(&g_pooled[k * Bc + b]);
            #pragma unroll
            for (int c = 0; c < NCc; c++) part[c] += pv * ws[c * 512 + k];
        }
        #pragma unroll
        for (int c = 0; c < NCc; c++) redf[(kq * NCc + c) * Bc + b] = part[c];
        __syncthreads();
        for (int o = tid; o < Bc * NCc; o += NTHR) {
            int c = o >> 6, b2 = o & 63;
            float s_ = fc_b[c];
            #pragma unroll
            for (int q = 0; q < 8; q++) s_ += redf[(q * NCc + c) * Bc + b2];
            out[b2 * NCc + c] = s_;
        }
    }
}

// ---------------- launch ----------------
extern "C" void kernel_launch(void *const *d_in, const int *in_sizes, int n_in,
                              void *d_out, int out_size)
{
    (void)in_sizes; (void)n_in; (void)out_size;
    const float *x     = (const float *)d_in[0];
    const float *w_ih0 = (const float *)d_in[1];
    const float *w_hh0 = (const float *)d_in[2];
    const float *b_ih0 = (const float *)d_in[3];
    const float *b_hh0 = (const float *)d_in[4];
    const float *w_ih1 = (const float *)d_in[5];
    const float *w_hh1 = (const float *)d_in[6];
    const float *b_ih1 = (const float *)d_in[7];
    const float *b_hh1 = (const float *)d_in[8];
    const float *fc_w  = (const float *)d_in[9];
    const float *fc_b  = (const float *)d_in[10];
    float *out = (float *)d_out;

    // 120KB dynamic smem (86KB used): forces 1 block/SM so all 128 blocks are
    // co-resident (required by the software global barriers).
    const int smem = 120 * 1024;
    cudaFuncSetAttribute(bilstm_kernel, cudaFuncAttributeMaxDynamicSharedMemorySize, smem);

    bilstm_kernel<<<NBLK, NTHR, smem>>>(x, w_ih0, w_hh0, b_ih0, b_hh0,
                                        w_ih1, w_hh1, b_ih1, b_hh1,
                                        fc_w, fc_b, out);
}

// round 14
// speedup vs baseline: 1.5115x; 1.2096x over previous
#include <cuda_runtime.h>

#define NBLK 128
#define NTHR 512
#define Bc   64
#define Tc   1024
#define Hc   256
#define DINc 12
#define NCc  17

typedef unsigned long long u64;

// ---------------- static device scratch (no allocations allowed) ----------------
__device__ __align__(256) float g_xT[Tc * DINc * Bc];           // x transposed [t][k][b]
__device__ __align__(256) float g_out0[(size_t)Tc * 512 * Bc];  // layer-0 out [t][k][b]
__device__ __align__(256) float g_hbuf[2 * 2 * Hc * Bc];        // [dir][parity][j][b]
__device__ __align__(256) float g_pooled[512 * Bc];             // [k][b]
// Barrier state: per-dir (64 blocks each) + full (128 blocks). Padded apart.
__device__ unsigned g_cnt_d[2 * 32];
__device__ volatile unsigned g_sn_d[2 * 32];
__device__ unsigned g_cnt_f;
__device__ volatile unsigned g_sn_f;

// ---------------- helpers ----------------
__device__ __forceinline__ u64 pk2(float v) {
    u64 r; asm("mov.b64 %0, {%1, %2};" : "=l"(r) : "f"(v), "f"(v)); return r;
}
__device__ __forceinline__ void fma2(u64 &a, u64 x, u64 w) {
    asm("fma.rn.f32x2 %0, %1, %2, %0;" : "+l"(a) : "l"(x), "l"(w));
}
__device__ __forceinline__ float sigm_(float x) { return 1.0f / (1.0f + __expf(-x)); }
__device__ __forceinline__ float tanh_(float x) {
    float e = __expf(-2.0f * fabsf(x));
    float r = (1.0f - e) / (1.0f + e);
    return x >= 0.f ? r : -r;
}

__device__ __forceinline__ unsigned smaddr(const void *p) {
    return (unsigned)__cvta_generic_to_shared(p);
}
__device__ __forceinline__ void cpa16(unsigned dst, const void *src) {
    asm volatile("cp.async.cg.shared.global [%0], [%1], 16;" :: "r"(dst), "l"(src));
}
#define CP_COMMIT()  asm volatile("cp.async.commit_group;")
#define CP_WAIT0()   asm volatile("cp.async.wait_group 0;")
#define CP_WAIT1()   asm volatile("cp.async.wait_group 1;")

// CG-style split barrier (proven round-12/13). bar_arrive by tid0 after
// __syncthreads(); bar_wait spins on the monotone sense then syncs.
__device__ __forceinline__ void bar_arrive(unsigned *cnt, volatile unsigned *gs,
                                           unsigned tgt, unsigned n) {
    __threadfence();
    if (atomicAdd(cnt, 1u) == n - 1u) {
        *cnt = 0u;
        __threadfence();
        *gs = tgt;
    }
}
__device__ __forceinline__ void bar_wait(volatile unsigned *gs, unsigned tgt) {
    if (threadIdx.x == 0) {
        while ((int)(*gs - tgt) < 0) { }
        __threadfence();   // acquire
    }
    __syncthreads();
}

// acc[rr*2 + j] += A_j * w_rr   (4 rows x 4 batches, batches as 2 u64 pairs)
__device__ __forceinline__ void mac8(u64 *acc, float4 wv, ulonglong2 A) {
    u64 w0 = pk2(wv.x), w1 = pk2(wv.y), w2 = pk2(wv.z), w3 = pk2(wv.w);
    fma2(acc[0], A.x, w0); fma2(acc[1], A.y, w0);
    fma2(acc[2], A.x, w1); fma2(acc[3], A.y, w1);
    fma2(acc[4], A.x, w2); fma2(acc[5], A.y, w2);
    fma2(acc[6], A.x, w3); fma2(acc[7], A.y, w3);
}

// ---------------- one bidirectional-LSTM phase ----------------
// Block gb: dir = gb>>6, owns 4 hidden units ub..ub+3 (16 gate rows in shared,
// transposed). Activations are STAGED into smem via cp.async (deep async
// pipeline — kills the MLP-4 L2-latency wall of direct __ldcg loops), then
// consumed with LDS.128. Split barrier: arrive after pointwise, next step's
// x-part staged+computed in the shadow, wait just before the h-part.
template <int KLIN, bool PH1>
__device__ void run_phase(
    int dir, int ub, int tid,
    const float *__restrict__ inbase,
    const float *__restrict__ w_ih, const float *__restrict__ w_hh,
    const float *__restrict__ b_ih, const float *__restrict__ b_hh,
    float *ws, float *stage, u64 *red,
    unsigned &sd, unsigned &sf, float &pool)
{
    constexpr int KLEN = KLIN + Hc;

    // Stage weights transposed: ws[k*16 + r]
    for (int idx = tid; idx < 16 * KLEN; idx += NTHR) {
        int r = idx / KLEN, k = idx - r * KLEN;
        int grow = (r >> 2) * Hc + ub + (r & 3);
        float v = (k < KLIN) ? w_ih[(size_t)(dir * 1024 + grow) * KLIN + k]
                             : w_hh[(size_t)(dir * 1024 + grow) * Hc + (k - KLIN)];
        ws[k * 16 + r] = v;
    }

    // Consumer-side per-thread state: cell state + 4 gate biases in registers.
    const int uu = tid >> 6, bb = tid & 63;
    float creg = 0.f;
    float bs[4] = {0.f, 0.f, 0.f, 0.f};
    int cbase = 0;
    if (tid < 256) {
        #pragma unroll
        for (int g = 0; g < 4; g++) {
            int bi = dir * 1024 + g * Hc + ub + uu;
            bs[g] = b_ih[bi] + b_hh[bi];
        }
        __stcg(&g_hbuf[((dir * 2 + 0) * Hc + ub + uu) * Bc + bb], 0.f);
        int bh2 = bb >> 5, bg2 = (bb & 31) >> 2, jp = (bb & 3) >> 1, lh = bb & 1;
        cbase = (bh2 * 256 + bg2) * 18 + uu * 4 + jp * 2 + lh;
    }
    __syncthreads();
    ++sf;
    if (tid == 0) bar_arrive(&g_cnt_f, &g_sn_f, sf, NBLK);
    bar_wait(&g_sn_f, sf);   // prev phase outputs + inits visible chip-wide

    const int lane = tid & 31;
    const int ks   = (tid >> 5) & 7;     // k-segment (stride 8)
    const int bh   = tid >> 8;           // batch half (0/1)
    const int rg   = lane >> 3;          // gate (rows rg*4..rg*4+3)
    const int bg   = lane & 7;
    const int boff = bh * 32 + bg * 4;
    const float *wsh  = ws + KLIN * 16;  // h-rows of the weight tile
    const float *redf = (const float *)red;
    volatile unsigned *gsd = &g_sn_d[dir * 32];
    unsigned *cntd = &g_cnt_d[dir * 32];
    const unsigned sbase = smaddr(stage);

    u64 acc[8];

    // ---- staged x-part for step index sx (fills acc from zero) ----
    auto do_xpart = [&](int sx) {
        #pragma unroll
        for (int i = 0; i < 8; i++) acc[i] = 0ull;
        const int t = dir ? (Tc - 1 - sx) : sx;
        const char *xsrc = (const char *)(inbase + (size_t)t * KLIN * Bc);
        if (KLIN == DINc) {              // 3KB, single chunk
            for (int i = tid * 16; i < DINc * Bc * 4; i += NTHR * 16)
                cpa16(sbase + i, xsrc + i);
            CP_COMMIT(); CP_WAIT0();
            __syncthreads();
            #pragma unroll
            for (int k = ks; k < DINc; k += 8) {
                float4 wv = *(const float4 *)(ws + k * 16 + rg * 4);
                ulonglong2 A = *(const ulonglong2 *)(stage + k * Bc + boff);
                mac8(acc, wv, A);
            }
            __syncthreads();
        } else {                          // 128KB: 4 chunks of 32KB, ping-pong
            for (int i = tid * 16; i < 32768; i += NTHR * 16)
                cpa16(sbase + i, xsrc + i);
            CP_COMMIT();
            #pragma unroll
            for (int c = 0; c < 4; c++) {
                if (c < 3) {
                    unsigned doff = ((c + 1) & 1) * 32768u;
                    const char *src = xsrc + (size_t)(c + 1) * 32768;
                    for (int i = tid * 16; i < 32768; i += NTHR * 16)
                        cpa16(sbase + doff + i, src + i);
                    CP_COMMIT(); CP_WAIT1();
                } else {
                    CP_WAIT0();
                }
                __syncthreads();
                const float *xs = stage + (c & 1) * 8192;
                const float *wsc = ws + c * 128 * 16;
                #pragma unroll 8
                for (int k = ks; k < 128; k += 8) {
                    float4 wv = *(const float4 *)(wsc + k * 16 + rg * 4);
                    ulonglong2 A = *(const ulonglong2 *)(xs + k * Bc + boff);
                    mac8(acc, wv, A);
                }
                __syncthreads();
            }
        }
    };

    do_xpart(0);

    for (int s = 0;;) {
        if (s > 0) bar_wait(gsd, sd);    // h(s-1) now visible

        // ---- h-part: stage full 64KB h-slab async, compute from smem ----
        {
            const char *hsrc = (const char *)(g_hbuf + (dir * 2 + (s & 1)) * Hc * Bc);
            for (int i = tid * 16; i < Hc * Bc * 4; i += NTHR * 16)
                cpa16(sbase + i, hsrc + i);
            CP_COMMIT(); CP_WAIT0();
            __syncthreads();
            #pragma unroll 8
            for (int k = ks; k < Hc; k += 8) {
                float4 wv = *(const float4 *)(wsh + k * 16 + rg * 4);
                ulonglong2 A = *(const ulonglong2 *)(stage + k * Bc + boff);
                mac8(acc, wv, A);
            }
        }

        // ---- publish partials; merged gather + pointwise (tid<256) ----
        #pragma unroll
        for (int i = 0; i < 8; i++) red[tid * 9 + i] = acc[i];
        __syncthreads();
        const int t = dir ? (Tc - 1 - s) : s;
        if (tid < 256) {
            float gv[4];
            #pragma unroll
            for (int g = 0; g < 4; g++) {
                float sacc = bs[g];
                #pragma unroll
                for (int q = 0; q < 8; q++)
                    sacc += redf[cbase + g * 144 + q * 576];
                gv[g] = sacc;
            }
            float cc = sigm_(gv[1]) * creg + sigm_(gv[0]) * tanh_(gv[2]);
            float hh = sigm_(gv[3]) * tanh_(cc);
            creg = cc;
            __stcg(&g_hbuf[((dir * 2 + ((s & 1) ^ 1)) * Hc + ub + uu) * Bc + bb], hh);
            if (!PH1) __stcg(&g_out0[((size_t)t * 512 + dir * Hc + ub + uu) * Bc + bb], hh);
            else      pool += hh;
        }
        __syncthreads();
        ++sd;
        if (tid == 0) bar_arrive(cntd, gsd, sd, 64);   // arrive; wait deferred

        if (++s == Tc) break;
        do_xpart(s);      // next step's x-part in the barrier shadow
    }
}

// ---------------- main persistent kernel ----------------
__global__ void __launch_bounds__(NTHR, 1) bilstm_kernel(
    const float *__restrict__ x,
    const float *__restrict__ w_ih0, const float *__restrict__ w_hh0,
    const float *__restrict__ b_ih0, const float *__restrict__ b_hh0,
    const float *__restrict__ w_ih1, const float *__restrict__ w_hh1,
    const float *__restrict__ b_ih1, const float *__restrict__ b_hh1,
    const float *__restrict__ fc_w, const float *__restrict__ fc_b,
    float *__restrict__ out)
{
    extern __shared__ __align__(16) float sm[];
    float *ws    = sm;                     // 12288 floats (48KB)
    float *stage = sm + 12288;             // 16384 floats (64KB) act staging
    u64   *red   = (u64 *)(sm + 12288 + 16384);   // 4608 u64 (36KB)

    const int tid = threadIdx.x;
    const int gb  = blockIdx.x;
    const int dir = gb >> 6;
    const int ub  = (gb & 63) * 4;

    unsigned sd = g_sn_d[dir * 32];
    unsigned sf = g_sn_f;

    // transpose x -> g_xT[t][k][b]
    for (int i = gb * NTHR + tid; i < Tc * DINc * Bc; i += NBLK * NTHR) {
        int b = i & 63;
        int j = i >> 6;
        int k = j % DINc;
        int t = j / DINc;
        g_xT[i] = x[((size_t)b * Tc + t) * DINc + k];
    }

    float pool = 0.f;
    run_phase<DINc, false>(dir, ub, tid, g_xT,  w_ih0, w_hh0, b_ih0, b_hh0,
                           ws, stage, red, sd, sf, pool);
    run_phase<512,  true >(dir, ub, tid, g_out0, w_ih1, w_hh1, b_ih1, b_hh1,
                           ws, stage, red, sd, sf, pool);

    // mean-pool write (matches pointwise ownership)
    if (tid < 256) {
        int u = tid >> 6, b = tid & 63;
        __stcg(&g_pooled[(dir * Hc + ub + u) * Bc + b], pool * (1.0f / (float)Tc));
    }
    __syncthreads();
    ++sf;
    if (tid == 0) bar_arrive(&g_cnt_f, &g_sn_f, sf, NBLK);

    // final FC on block 0 (64x17 dots of length 512, k-split 8 ways)
    if (gb == 0) {
        bar_wait(&g_sn_f, sf);
        for (int i = tid; i < NCc * 512; i += NTHR) ws[i] = fc_w[i];
        __syncthreads();
        float *redf = (float *)red;
        int b = tid & 63, kq = tid >> 6;
        float part[NCc];
        #pragma unroll
        for (int c = 0; c < NCc; c++) part[c] = 0.f;
        for (int k = kq * 64; k < kq * 64 + 64; k++) {
            float pv = __ldcg(&g_pooled[k * Bc + b]);
            #pragma unroll
            for (int c = 0; c < NCc; c++) part[c] += pv * ws[c * 512 + k];
        }
        #pragma unroll
        for (int c = 0; c < NCc; c++) redf[(kq * NCc + c) * Bc + b] = part[c];
        __syncthreads();
        for (int o = tid; o < Bc * NCc; o += NTHR) {
            int c = o >> 6, b2 = o & 63;
            float s_ = fc_b[c];
            #pragma unroll
            for (int q = 0; q < 8; q++) s_ += redf[(q * NCc + c) * Bc + b2];
            out[b2 * NCc + c] = s_;
        }
    }
}

// ---------------- launch ----------------
extern "C" void kernel_launch(void *const *d_in, const int *in_sizes, int n_in,
                              void *d_out, int out_size)
{
    (void)in_sizes; (void)n_in; (void)out_size;
    const float *x     = (const float *)d_in[0];
    const float *w_ih0 = (const float *)d_in[1];
    const float *w_hh0 = (const float *)d_in[2];
    const float *b_ih0 = (const float *)d_in[3];
    const float *b_hh0 = (const float *)d_in[4];
    const float *w_ih1 = (const float *)d_in[5];
    const float *w_hh1 = (const float *)d_in[6];
    const float *b_ih1 = (const float *)d_in[7];
    const float *b_hh1 = (const float *)d_in[8];
    const float *fc_w  = (const float *)d_in[9];
    const float *fc_b  = (const float *)d_in[10];
    float *out = (float *)d_out;

    // 148KB dynamic smem (ws 48 + stage 64 + red 36): 1 block/SM, all 128
    // blocks co-resident (required by the software global barriers).
    const int smem = (12288 + 16384 + 9216) * 4;
    cudaFuncSetAttribute(bilstm_kernel, cudaFuncAttributeMaxDynamicSharedMemorySize, smem);

    bilstm_kernel<<<NBLK, NTHR, smem>>>(x, w_ih0, w_hh0, b_ih0, b_hh0,
                                        w_ih1, w_hh1, b_ih1, b_hh1,
                                        fc_w, fc_b, out);
}

// round 15
// speedup vs baseline: 1.6327x; 1.0802x over previous
#include <cuda_runtime.h>

#define NBLK 128
#define NTHR 512
#define Bc   64
#define Tc   1024
#define Hc   256
#define DINc 12
#define NCc  17

typedef unsigned long long u64;

// ---------------- static device scratch (no allocations allowed) ----------------
__device__ __align__(256) float g_xT[Tc * DINc * Bc];           // x transposed [t][k][b]
__device__ __align__(256) float g_out0[(size_t)Tc * 512 * Bc];  // layer-0 out [t][k][b]
__device__ __align__(256) float g_hbuf[2 * 2 * Hc * Bc];        // [dir][parity][j][b]
__device__ __align__(256) float g_pooled[512 * Bc];             // [k][b]
// Distributed flag barriers: one monotone flag per block, 128B padded.
// No counters, no resets, no atomics — a block ARRIVES by storing its round
// number; waiters poll the flags of all blocks they depend on.
__device__ volatile unsigned g_fd[NBLK * 32];   // per-dir step barrier flags
__device__ volatile unsigned g_ff[NBLK * 32];   // full-grid barrier flags

// ---------------- helpers ----------------
__device__ __forceinline__ u64 pk2(float v) {
    u64 r; asm("mov.b64 %0, {%1, %2};" : "=l"(r) : "f"(v), "f"(v)); return r;
}
__device__ __forceinline__ void fma2(u64 &a, u64 x, u64 w) {
    asm("fma.rn.f32x2 %0, %1, %2, %0;" : "+l"(a) : "l"(x), "l"(w));
}
__device__ __forceinline__ float sigm_(float x) { return 1.0f / (1.0f + __expf(-x)); }
__device__ __forceinline__ float tanh_(float x) {
    float e = __expf(-2.0f * fabsf(x));
    float r = (1.0f - e) / (1.0f + e);
    return x >= 0.f ? r : -r;
}

__device__ __forceinline__ unsigned smaddr(const void *p) {
    return (unsigned)__cvta_generic_to_shared(p);
}
__device__ __forceinline__ void cpa16(unsigned dst, const void *src) {
    asm volatile("cp.async.cg.shared.global [%0], [%1], 16;" :: "r"(dst), "l"(src));
}
#define CP_COMMIT()  asm volatile("cp.async.commit_group;")
#define CP_WAIT0()   asm volatile("cp.async.wait_group 0;")
#define CP_WAIT1()   asm volatile("cp.async.wait_group 1;")

// Arrive: tid0 only, AFTER __syncthreads() (CTA stores issued) — fence then
// publish own flag. Wait: thread i (<n) spins on peer i's flag, then CTA sync.
__device__ __forceinline__ void flag_arrive(volatile unsigned *flg, unsigned v) {
    __threadfence();
    *flg = v;
}
__device__ __forceinline__ void flag_wait(volatile unsigned *base, int n,
                                          unsigned v, int tid) {
    if (tid < n) {
        volatile unsigned *p = base + tid * 32;
        while ((int)(*p - v) < 0) { }
        __threadfence();   // acquire
    }
    __syncthreads();
}

// acc[rr*2 + j] += A_j * w_rr   (4 rows x 4 batches, batches as 2 u64 pairs)
__device__ __forceinline__ void mac8(u64 *acc, float4 wv, ulonglong2 A) {
    u64 w0 = pk2(wv.x), w1 = pk2(wv.y), w2 = pk2(wv.z), w3 = pk2(wv.w);
    fma2(acc[0], A.x, w0); fma2(acc[1], A.y, w0);
    fma2(acc[2], A.x, w1); fma2(acc[3], A.y, w1);
    fma2(acc[4], A.x, w2); fma2(acc[5], A.y, w2);
    fma2(acc[6], A.x, w3); fma2(acc[7], A.y, w3);
}

// ---------------- one bidirectional-LSTM phase ----------------
// Block gb: dir = gb>>6, owns 4 hidden units ub..ub+3 (16 gate rows in shared,
// transposed). Activations staged via cp.async, consumed from smem.
// Split barrier: flag-arrive after pointwise; next step's first x chunk is
// issued EARLY (right after h-partials publish), transfers overlap the
// gather/pointwise/barrier, and the x-MACs run in the barrier shadow.
template <int KLIN, bool PH1>
__device__ void run_phase(
    int dir, int ub, int tid, int gb,
    const float *__restrict__ inbase,
    const float *__restrict__ w_ih, const float *__restrict__ w_hh,
    const float *__restrict__ b_ih, const float *__restrict__ b_hh,
    float *ws, float *stage, u64 *red,
    unsigned &sd, unsigned &sf, float &pool)
{
    constexpr int KLEN = KLIN + Hc;

    // Stage weights transposed: ws[k*16 + r]
    for (int idx = tid; idx < 16 * KLEN; idx += NTHR) {
        int r = idx / KLEN, k = idx - r * KLEN;
        int grow = (r >> 2) * Hc + ub + (r & 3);
        float v = (k < KLIN) ? w_ih[(size_t)(dir * 1024 + grow) * KLIN + k]
                             : w_hh[(size_t)(dir * 1024 + grow) * Hc + (k - KLIN)];
        ws[k * 16 + r] = v;
    }

    // Consumer-side per-thread state: cell state + 4 gate biases in registers.
    const int uu = tid >> 6, bb = tid & 63;
    float creg = 0.f;
    float bs[4] = {0.f, 0.f, 0.f, 0.f};
    int cbase = 0;
    if (tid < 256) {
        #pragma unroll
        for (int g = 0; g < 4; g++) {
            int bi = dir * 1024 + g * Hc + ub + uu;
            bs[g] = b_ih[bi] + b_hh[bi];
        }
        __stcg(&g_hbuf[((dir * 2 + 0) * Hc + ub + uu) * Bc + bb], 0.f);
        int bh2 = bb >> 5, bg2 = (bb & 31) >> 2, jp = (bb & 3) >> 1, lh = bb & 1;
        cbase = (bh2 * 256 + bg2) * 18 + uu * 4 + jp * 2 + lh;
    }
    __syncthreads();
    ++sf;
    if (tid == 0) flag_arrive(&g_ff[gb * 32], sf);
    flag_wait(g_ff, NBLK, sf, tid);   // prev phase outputs + inits visible

    const int lane = tid & 31;
    const int ks   = (tid >> 5) & 7;     // k-segment (stride 8)
    const int bh   = tid >> 8;           // batch half (0/1)
    const int rg   = lane >> 3;          // gate (rows rg*4..rg*4+3)
    const int bg   = lane & 7;
    const int boff = bh * 32 + bg * 4;
    const float *wsh  = ws + KLIN * 16;  // h-rows of the weight tile
    const float *redf = (const float *)red;
    volatile unsigned *myfd = &g_fd[gb * 32];
    volatile unsigned *fdbase = &g_fd[(dir * 64) * 32];
    const unsigned sbase = smaddr(stage);

    u64 acc[8];

    // Issue the first x chunk (or whole x for phase 0) of step sx. No wait.
    auto issue_x0 = [&](int sx) {
        const int t = dir ? (Tc - 1 - sx) : sx;
        const char *xsrc = (const char *)(inbase + (size_t)t * KLIN * Bc);
        const int bytes = (KLIN == DINc) ? (DINc * Bc * 4) : 32768;
        for (int i = tid * 16; i < bytes; i += NTHR * 16)
            cpa16(sbase + i, xsrc + i);
        CP_COMMIT();
    };

    // Consume step sx's x (chunk0 already committed); fills acc from zero.
    auto xpart_compute = [&](int sx) {
        #pragma unroll
        for (int i = 0; i < 8; i++) acc[i] = 0ull;
        if (KLIN == DINc) {
            CP_WAIT0();
            __syncthreads();
            #pragma unroll
            for (int k = ks; k < DINc; k += 8) {
                float4 wv = *(const float4 *)(ws + k * 16 + rg * 4);
                ulonglong2 A = *(const ulonglong2 *)(stage + k * Bc + boff);
                mac8(acc, wv, A);
            }
            __syncthreads();
        } else {
            const int t = dir ? (Tc - 1 - sx) : sx;
            const char *xsrc = (const char *)(inbase + (size_t)t * KLIN * Bc);
            #pragma unroll
            for (int c = 0; c < 4; c++) {
                if (c < 3) {
                    unsigned doff = ((c + 1) & 1) * 32768u;
                    const char *src = xsrc + (size_t)(c + 1) * 32768;
                    for (int i = tid * 16; i < 32768; i += NTHR * 16)
                        cpa16(sbase + doff + i, src + i);
                    CP_COMMIT(); CP_WAIT1();
                } else {
                    CP_WAIT0();
                }
                __syncthreads();
                const float *xs = stage + (c & 1) * 8192;
                const float *wsc = ws + c * 128 * 16;
                #pragma unroll 8
                for (int k = ks; k < 128; k += 8) {
                    float4 wv = *(const float4 *)(wsc + k * 16 + rg * 4);
                    ulonglong2 A = *(const ulonglong2 *)(xs + k * Bc + boff);
                    mac8(acc, wv, A);
                }
                __syncthreads();
            }
        }
    };

    issue_x0(0);
    xpart_compute(0);

    for (int s = 0;;) {
        if (s > 0) flag_wait(fdbase, 64, sd, tid);    // h(s-1) now visible

        // ---- h-part: stage full 64KB h-slab async, compute from smem ----
        {
            const char *hsrc = (const char *)(g_hbuf + (dir * 2 + (s & 1)) * Hc * Bc);
            for (int i = tid * 16; i < Hc * Bc * 4; i += NTHR * 16)
                cpa16(sbase + i, hsrc + i);
            CP_COMMIT(); CP_WAIT0();
            __syncthreads();
            #pragma unroll 8
            for (int k = ks; k < Hc; k += 8) {
                float4 wv = *(const float4 *)(wsh + k * 16 + rg * 4);
                ulonglong2 A = *(const ulonglong2 *)(stage + k * Bc + boff);
                mac8(acc, wv, A);
            }
        }

        // ---- publish partials ----
        #pragma unroll
        for (int i = 0; i < 8; i++) red[tid * 9 + i] = acc[i];
        __syncthreads();          // all warps done with stage -> safe to refill

        // ---- EARLY issue of next step's first x chunk (overlaps barrier) ----
        if (s + 1 < Tc) issue_x0(s + 1);

        // ---- merged gather + pointwise (tid<256) ----
        const int t = dir ? (Tc - 1 - s) : s;
        if (tid < 256) {
            float gv[4];
            #pragma unroll
            for (int g = 0; g < 4; g++) {
                float sacc = bs[g];
                #pragma unroll
                for (int q = 0; q < 8; q++)
                    sacc += redf[cbase + g * 144 + q * 576];
                gv[g] = sacc;
            }
            float cc = sigm_(gv[1]) * creg + sigm_(gv[0]) * tanh_(gv[2]);
            float hh = sigm_(gv[3]) * tanh_(cc);
            creg = cc;
            __stcg(&g_hbuf[((dir * 2 + ((s & 1) ^ 1)) * Hc + ub + uu) * Bc + bb], hh);
            if (!PH1) __stcg(&g_out0[((size_t)t * 512 + dir * Hc + ub + uu) * Bc + bb], hh);
            else      pool += hh;
        }
        __syncthreads();
        ++sd;
        if (tid == 0) flag_arrive(myfd, sd);   // arrive; wait deferred

        if (++s == Tc) break;
        xpart_compute(s);        // next step's x-MACs in the barrier shadow
    }
}

// ---------------- main persistent kernel ----------------
__global__ void __launch_bounds__(NTHR, 1) bilstm_kernel(
    const float *__restrict__ x,
    const float *__restrict__ w_ih0, const float *__restrict__ w_hh0,
    const float *__restrict__ b_ih0, const float *__restrict__ b_hh0,
    const float *__restrict__ w_ih1, const float *__restrict__ w_hh1,
    const float *__restrict__ b_ih1, const float *__restrict__ b_hh1,
    const float *__restrict__ fc_w, const float *__restrict__ fc_b,
    float *__restrict__ out)
{
    extern __shared__ __align__(16) float sm[];
    float *ws    = sm;                     // 12288 floats (48KB)
    float *stage = sm + 12288;             // 16384 floats (64KB) act staging
    u64   *red   = (u64 *)(sm + 12288 + 16384);   // 4608 u64 (36KB)

    const int tid = threadIdx.x;
    const int gb  = blockIdx.x;
    const int dir = gb >> 6;
    const int ub  = (gb & 63) * 4;

    // Monotone round mirrors: own flags (all equal across blocks at launch).
    unsigned sd = g_fd[gb * 32];
    unsigned sf = g_ff[gb * 32];

    // transpose x -> g_xT[t][k][b]
    for (int i = gb * NTHR + tid; i < Tc * DINc * Bc; i += NBLK * NTHR) {
        int b = i & 63;
        int j = i >> 6;
        int k = j % DINc;
        int t = j / DINc;
        g_xT[i] = x[((size_t)b * Tc + t) * DINc + k];
    }

    float pool = 0.f;
    run_phase<DINc, false>(dir, ub, tid, gb, g_xT,  w_ih0, w_hh0, b_ih0, b_hh0,
                           ws, stage, red, sd, sf, pool);
    run_phase<512,  true >(dir, ub, tid, gb, g_out0, w_ih1, w_hh1, b_ih1, b_hh1,
                           ws, stage, red, sd, sf, pool);

    // mean-pool write (matches pointwise ownership)
    if (tid < 256) {
        int u = tid >> 6, b = tid & 63;
        __stcg(&g_pooled[(dir * Hc + ub + u) * Bc + b], pool * (1.0f / (float)Tc));
    }
    __syncthreads();
    ++sf;
    if (tid == 0) flag_arrive(&g_ff[gb * 32], sf);

    // final FC on block 0 (64x17 dots of length 512, k-split 8 ways)
    if (gb == 0) {
        flag_wait(g_ff, NBLK, sf, tid);
        for (int i = tid; i < NCc * 512; i += NTHR) ws[i] = fc_w[i];
        __syncthreads();
        float *redf = (float *)red;
        int b = tid & 63, kq = tid >> 6;
        float part[NCc];
        #pragma unroll
        for (int c = 0; c < NCc; c++) part[c] = 0.f;
        for (int k = kq * 64; k < kq * 64 + 64; k++) {
            float pv = __ldcg(&g_pooled[k * Bc + b]);
            #pragma unroll
            for (int c = 0; c < NCc; c++) part[c] += pv * ws[c * 512 + k];
        }
        #pragma unroll
        for (int c = 0; c < NCc; c++) redf[(kq * NCc + c) * Bc + b] = part[c];
        __syncthreads();
        for (int o = tid; o < Bc * NCc; o += NTHR) {
            int c = o >> 6, b2 = o & 63;
            float s_ = fc_b[c];
            #pragma unroll
            for (int q = 0; q < 8; q++) s_ += redf[(q * NCc + c) * Bc + b2];
            out[b2 * NCc + c] = s_;
        }
    }
}

// ---------------- launch ----------------
extern "C" void kernel_launch(void *const *d_in, const int *in_sizes, int n_in,
                              void *d_out, int out_size)
{
    (void)in_sizes; (void)n_in; (void)out_size;
    const float *x     = (const float *)d_in[0];
    const float *w_ih0 = (const float *)d_in[1];
    const float *w_hh0 = (const float *)d_in[2];
    const float *b_ih0 = (const float *)d_in[3];
    const float *b_hh0 = (const float *)d_in[4];
    const float *w_ih1 = (const float *)d_in[5];
    const float *w_hh1 = (const float *)d_in[6];
    const float *b_ih1 = (const float *)d_in[7];
    const float *b_hh1 = (const float *)d_in[8];
    const float *fc_w  = (const float *)d_in[9];
    const float *fc_b  = (const float *)d_in[10];
    float *out = (float *)d_out;

    // 148KB dynamic smem (ws 48 + stage 64 + red 36): 1 block/SM, all 128
    // blocks co-resident (required by the software global barriers).
    const int smem = (12288 + 16384 + 9216) * 4;
    cudaFuncSetAttribute(bilstm_kernel, cudaFuncAttributeMaxDynamicSharedMemorySize, smem);

    bilstm_kernel<<<NBLK, NTHR, smem>>>(x, w_ih0, w_hh0, b_ih0, b_hh0,
                                        w_ih1, w_hh1, b_ih1, b_hh1,
                                        fc_w, fc_b, out);
}

// round 17
// speedup vs baseline: 1.6591x; 1.0162x over previous
#include <cuda_runtime.h>

#define NBLK 128
#define NTHR 512
#define Bc   64
#define Tc   1024
#define Hc   256
#define DINc 12
#define NCc  17

typedef unsigned long long u64;

// ---------------- static device scratch (no allocations allowed) ----------------
__device__ __align__(256) float g_xT[Tc * DINc * Bc];           // x transposed [t][k][b]
__device__ __align__(256) float g_out0[(size_t)Tc * 512 * Bc];  // layer-0 out [t][k][b]
__device__ __align__(256) float g_hbuf[2 * 2 * Hc * Bc];        // [dir][parity][j][b]
__device__ __align__(256) float g_pooled[512 * Bc];             // [k][b]
// Distributed flag barriers: one monotone flag per block, 128B padded.
__device__ volatile unsigned g_fd[NBLK * 32];   // per-dir step barrier flags
__device__ volatile unsigned g_ff[NBLK * 32];   // full-grid barrier flags

// ---------------- helpers ----------------
__device__ __forceinline__ u64 pk2(float v) {
    u64 r; asm("mov.b64 %0, {%1, %2};" : "=l"(r) : "f"(v), "f"(v)); return r;
}
__device__ __forceinline__ void fma2(u64 &a, u64 x, u64 w) {
    asm("fma.rn.f32x2 %0, %1, %2, %0;" : "+l"(a) : "l"(x), "l"(w));
}
__device__ __forceinline__ float sigm_(float x) { return 1.0f / (1.0f + __expf(-x)); }
__device__ __forceinline__ float tanh_(float x) {
    float e = __expf(-2.0f * fabsf(x));
    float r = (1.0f - e) / (1.0f + e);
    return x >= 0.f ? r : -r;
}

__device__ __forceinline__ unsigned smaddr(const void *p) {
    return (unsigned)__cvta_generic_to_shared(p);
}
__device__ __forceinline__ void cpa16(unsigned dst, const void *src) {
    asm volatile("cp.async.cg.shared.global [%0], [%1], 16;" :: "r"(dst), "l"(src));
}
#define CP_COMMIT()  asm volatile("cp.async.commit_group;")
#define CP_WAIT0()   asm volatile("cp.async.wait_group 0;")
#define CP_WAIT1()   asm volatile("cp.async.wait_group 1;")
#define CP_WAIT2()   asm volatile("cp.async.wait_group 2;")

// Arrive: tid0 only, AFTER __syncthreads(). Wait: thread i spins on peer i.
__device__ __forceinline__ void flag_arrive(volatile unsigned *flg, unsigned v) {
    __threadfence();
    *flg = v;
}
__device__ __forceinline__ void flag_wait(volatile unsigned *base, int n,
                                          unsigned v, int tid) {
    if (tid < n) {
        volatile unsigned *p = base + tid * 32;
        while ((int)(*p - v) < 0) { }
        __threadfence();   // acquire
    }
    __syncthreads();
}

// acc[rr*2 + j] += A_j * w_rr   (4 rows x 4 batches, batches as 2 u64 pairs)
__device__ __forceinline__ void mac8(u64 *acc, float4 wv, ulonglong2 A) {
    u64 w0 = pk2(wv.x), w1 = pk2(wv.y), w2 = pk2(wv.z), w3 = pk2(wv.w);
    fma2(acc[0], A.x, w0); fma2(acc[1], A.y, w0);
    fma2(acc[2], A.x, w1); fma2(acc[3], A.y, w1);
    fma2(acc[4], A.x, w2); fma2(acc[5], A.y, w2);
    fma2(acc[6], A.x, w3); fma2(acc[7], A.y, w3);
}

// ---------------- one bidirectional-LSTM phase ----------------
// Block gb: dir = gb>>6, owns 4 hidden units ub..ub+3 (16 gate rows in shared,
// transposed). h and x have DISJOINT staging buffers; h is ping-ponged in two
// 32KB cp.async groups so MACs on half 0 overlap half 1's transfer; next
// step's first x chunk is committed at the TOP of the step (3rd group), so its
// transfer overlaps h-compute + pointwise + barrier, and the shadow x-MACs
// start hot. cp group accounting: [h0, h1, (x0)] -> WAIT2/WAIT1 when x0
// present, WAIT1/WAIT0 on the last step.
template <int KLIN, bool PH1>
__device__ void run_phase(
    int dir, int ub, int tid, int gb,
    const float *__restrict__ inbase,
    const float *__restrict__ w_ih, const float *__restrict__ w_hh,
    const float *__restrict__ b_ih, const float *__restrict__ b_hh,
    float *ws, float *hstage, float *xstage, u64 *red,
    unsigned &sd, unsigned &sf, float &pool)
{
    constexpr int KLEN = KLIN + Hc;

    // Stage weights transposed: ws[k*16 + r]
    for (int idx = tid; idx < 16 * KLEN; idx += NTHR) {
        int r = idx / KLEN, k = idx - r * KLEN;
        int grow = (r >> 2) * Hc + ub + (r & 3);
        float v = (k < KLIN) ? w_ih[(size_t)(dir * 1024 + grow) * KLIN + k]
                             : w_hh[(size_t)(dir * 1024 + grow) * Hc + (k - KLIN)];
        ws[k * 16 + r] = v;
    }

    // Consumer-side per-thread state: cell state + 4 gate biases in registers.
    const int uu = tid >> 6, bb = tid & 63;
    float creg = 0.f;
    float bs[4] = {0.f, 0.f, 0.f, 0.f};
    int cbase = 0;
    if (tid < 256) {
        #pragma unroll
        for (int g = 0; g < 4; g++) {
            int bi = dir * 1024 + g * Hc + ub + uu;
            bs[g] = b_ih[bi] + b_hh[bi];
        }
        __stcg(&g_hbuf[((dir * 2 + 0) * Hc + ub + uu) * Bc + bb], 0.f);
        int bh2 = bb >> 5, bg2 = (bb & 31) >> 2, jp = (bb & 3) >> 1, lh = bb & 1;
        cbase = (bh2 * 256 + bg2) * 18 + uu * 4 + jp * 2 + lh;
    }
    __syncthreads();
    ++sf;
    if (tid == 0) flag_arrive(&g_ff[gb * 32], sf);
    flag_wait(g_ff, NBLK, sf, tid);   // prev phase outputs + inits visible

    const int lane = tid & 31;
    const int ks   = (tid >> 5) & 7;     // k-segment (stride 8)
    const int rg   = lane >> 3;          // gate (rows rg*4..rg*4+3)
    const int bg   = lane & 7;
    const int boff = (tid >> 8) * 32 + bg * 4;
    const float *wsh  = ws + KLIN * 16;  // h-rows of the weight tile
    const float *redf = (const float *)red;
    volatile unsigned *myfd = &g_fd[gb * 32];
    volatile unsigned *fdbase = &g_fd[(dir * 64) * 32];
    const unsigned hbase = smaddr(hstage);
    const unsigned xbase = smaddr(xstage);

    u64 acc[8];

    // Commit step sx's first x chunk (phase0: whole 3KB slab) into x region A.
    auto issue_x0 = [&](int sx) {
        const int t = dir ? (Tc - 1 - sx) : sx;
        const char *xsrc = (const char *)(inbase + (size_t)t * KLIN * Bc);
        const int bytes = (KLIN == DINc) ? (DINc * Bc * 4) : 32768;
        for (int i = tid * 16; i < bytes; i += NTHR * 16)
            cpa16(xbase + i, xsrc + i);
        CP_COMMIT();
    };

    // Consume step sx's x (chunk0 committed, sole pending group at entry).
    auto xpart_compute = [&](int sx) {
        #pragma unroll
        for (int i = 0; i < 8; i++) acc[i] = 0ull;
        if (KLIN == DINc) {
            CP_WAIT0();
            __syncthreads();
            #pragma unroll
            for (int k = ks; k < DINc; k += 8) {
                float4 wv = *(const float4 *)(ws + k * 16 + rg * 4);
                ulonglong2 A = *(const ulonglong2 *)(xstage + k * Bc + boff);
                mac8(acc, wv, A);
            }
            __syncthreads();
        } else {
            const int t = dir ? (Tc - 1 - sx) : sx;
            const char *xsrc = (const char *)(inbase + (size_t)t * KLIN * Bc);
            #pragma unroll
            for (int c = 0; c < 4; c++) {
                if (c < 3) {     // commit chunk c+1 into the other region
                    unsigned doff = ((c + 1) & 1) * 32768u;
                    const char *src = xsrc + (size_t)(c + 1) * 32768;
                    for (int i = tid * 16; i < 32768; i += NTHR * 16)
                        cpa16(xbase + doff + i, src + i);
                    CP_COMMIT(); CP_WAIT1();
                } else {
                    CP_WAIT0();
                }
                __syncthreads();
                const float *xs = xstage + (c & 1) * 8192;
                const float *wsc = ws + c * 128 * 16;
                #pragma unroll 8
                for (int k = ks; k < 128; k += 8) {
                    float4 wv = *(const float4 *)(wsc + k * 16 + rg * 4);
                    ulonglong2 A = *(const ulonglong2 *)(xs + k * Bc + boff);
                    mac8(acc, wv, A);
                }
                __syncthreads();
            }
        }
    };

    issue_x0(0);
    xpart_compute(0);

    for (int s = 0;;) {
        if (s > 0) flag_wait(fdbase, 64, sd, tid);    // h(s-1) now visible

        // ---- h staging: two 32KB halves + early x0 of next step ----
        const char *hsrc = (const char *)(g_hbuf + (dir * 2 + (s & 1)) * Hc * Bc);
        for (int i = tid * 16; i < 32768; i += NTHR * 16)
            cpa16(hbase + i, hsrc + i);
        CP_COMMIT();
        for (int i = tid * 16; i < 32768; i += NTHR * 16)
            cpa16(hbase + 32768u + i, hsrc + 32768 + i);
        CP_COMMIT();
        const bool have_x = (s + 1 < Tc);
        if (have_x) issue_x0(s + 1);       // 3rd group: overlaps everything below

        if (have_x) { CP_WAIT2(); } else { CP_WAIT1(); }
        __syncthreads();
        #pragma unroll 8
        for (int k = ks; k < 128; k += 8) {        // h half 0
            float4 wv = *(const float4 *)(wsh + k * 16 + rg * 4);
            ulonglong2 A = *(const ulonglong2 *)(hstage + k * Bc + boff);
            mac8(acc, wv, A);
        }
        if (have_x) { CP_WAIT1(); } else { CP_WAIT0(); }
        __syncthreads();
        #pragma unroll 8
        for (int k = 128 + ks; k < 256; k += 8) {  // h half 1
            float4 wv = *(const float4 *)(wsh + k * 16 + rg * 4);
            ulonglong2 A = *(const ulonglong2 *)(hstage + k * Bc + boff);
            mac8(acc, wv, A);
        }

        // ---- publish partials ----
        #pragma unroll
        for (int i = 0; i < 8; i++) red[tid * 9 + i] = acc[i];
        __syncthreads();

        // ---- merged gather + pointwise (tid<256) ----
        const int t = dir ? (Tc - 1 - s) : s;
        if (tid < 256) {
            float gv[4];
            #pragma unroll
            for (int g = 0; g < 4; g++) {
                float sacc = bs[g];
                #pragma unroll
                for (int q = 0; q < 8; q++)
                    sacc += redf[cbase + g * 144 + q * 576];
                gv[g] = sacc;
            }
            float cc = sigm_(gv[1]) * creg + sigm_(gv[0]) * tanh_(gv[2]);
            float hh = sigm_(gv[3]) * tanh_(cc);
            creg = cc;
            __stcg(&g_hbuf[((dir * 2 + ((s & 1) ^ 1)) * Hc + ub + uu) * Bc + bb], hh);
            if (!PH1) __stcg(&g_out0[((size_t)t * 512 + dir * Hc + ub + uu) * Bc + bb], hh);
            else      pool += hh;
        }
        __syncthreads();
        ++sd;
        if (tid == 0) flag_arrive(myfd, sd);   // arrive; wait deferred

        if (++s == Tc) break;
        xpart_compute(s);        // next step's x-MACs in the barrier shadow
    }
}

// ---------------- main persistent kernel ----------------
__global__ void __launch_bounds__(NTHR, 1) bilstm_kernel(
    const float *__restrict__ x,
    const float *__restrict__ w_ih0, const float *__restrict__ w_hh0,
    const float *__restrict__ b_ih0, const float *__restrict__ b_hh0,
    const float *__restrict__ w_ih1, const float *__restrict__ w_hh1,
    const float *__restrict__ b_ih1, const float *__restrict__ b_hh1,
    const float *__restrict__ fc_w, const float *__restrict__ fc_b,
    float *__restrict__ out)
{
    extern __shared__ __align__(16) float sm[];
    float *ws     = sm;                      // 12288 floats (48KB)
    float *hstage = sm + 12288;              // 16384 floats (64KB) h staging
    float *xstage = sm + 12288 + 16384;      // 16384 floats (64KB) x ping-pong
    u64   *red    = (u64 *)(sm + 12288 + 32768);   // 4608 u64 (36KB)

    const int tid = threadIdx.x;
    const int gb  = blockIdx.x;
    const int dir = gb >> 6;
    const int ub  = (gb & 63) * 4;

    // Monotone round mirrors: own flags (all equal across blocks at launch).
    unsigned sd = g_fd[gb * 32];
    unsigned sf = g_ff[gb * 32];

    // transpose x -> g_xT[t][k][b]
    for (int i = gb * NTHR + tid; i < Tc * DINc * Bc; i += NBLK * NTHR) {
        int b = i & 63;
        int j = i >> 6;
        int k = j % DINc;
        int t = j / DINc;
        g_xT[i] = x[((size_t)b * Tc + t) * DINc + k];
    }

    float pool = 0.f;
    run_phase<DINc, false>(dir, ub, tid, gb, g_xT,  w_ih0, w_hh0, b_ih0, b_hh0,
                           ws, hstage, xstage, red, sd, sf, pool);
    run_phase<512,  true >(dir, ub, tid, gb, g_out0, w_ih1, w_hh1, b_ih1, b_hh1,
                           ws, hstage, xstage, red, sd, sf, pool);

    // mean-pool write (matches pointwise ownership)
    if (tid < 256) {
        int u = tid >> 6, b = tid & 63;
        __stcg(&g_pooled[(dir * Hc + ub + u) * Bc + b], pool * (1.0f / (float)Tc));
    }
    __syncthreads();
    ++sf;
    if (tid == 0) flag_arrive(&g_ff[gb * 32], sf);

    // final FC on block 0 (64x17 dots of length 512, k-split 8 ways)
    if (gb == 0) {
        flag_wait(g_ff, NBLK, sf, tid);
        for (int i = tid; i < NCc * 512; i += NTHR) ws[i] = fc_w[i];
        __syncthreads();
        float *redf = (float *)red;
        int b = tid & 63, kq = tid >> 6;
        float part[NCc];
        #pragma unroll
        for (int c = 0; c < NCc; c++) part[c] = 0.f;
        for (int k = kq * 64; k < kq * 64 + 64; k++) {
            float pv = __ldcg(&g_pooled[k * Bc + b]);
            #pragma unroll
            for (int c = 0; c < NCc; c++) part[c] += pv * ws[c * 512 + k];
        }
        #pragma unroll
        for (int c = 0; c < NCc; c++) redf[(kq * NCc + c) * Bc + b] = part[c];
        __syncthreads();
        for (int o = tid; o < Bc * NCc; o += NTHR) {
            int c = o >> 6, b2 = o & 63;
            float s_ = fc_b[c];
            #pragma unroll
            for (int q = 0; q < 8; q++) s_ += redf[(q * NCc + c) * Bc + b2];
            out[b2 * NCc + c] = s_;
        }
    }
}

// ---------------- launch ----------------
extern "C" void kernel_launch(void *const *d_in, const int *in_sizes, int n_in,
                              void *d_out, int out_size)
{
    (void)in_sizes; (void)n_in; (void)out_size;
    const float *x     = (const float *)d_in[0];
    const float *w_ih0 = (const float *)d_in[1];
    const float *w_hh0 = (const float *)d_in[2];
    const float *b_ih0 = (const float *)d_in[3];
    const float *b_hh0 = (const float *)d_in[4];
    const float *w_ih1 = (const float *)d_in[5];
    const float *w_hh1 = (const float *)d_in[6];
    const float *b_ih1 = (const float *)d_in[7];
    const float *b_hh1 = (const float *)d_in[8];
    const float *fc_w  = (const float *)d_in[9];
    const float *fc_b  = (const float *)d_in[10];
    float *out = (float *)d_out;

    // 212KB dynamic smem (ws 48 + h 64 + x 64 + red 36): 1 block/SM, all 128
    // blocks co-resident (required by the software global barriers).
    const int smem = (12288 + 16384 + 16384 + 9216) * 4;
    cudaFuncSetAttribute(bilstm_kernel, cudaFuncAttributeMaxDynamicSharedMemorySize, smem);

    bilstm_kernel<<<NBLK, NTHR, smem>>>(x, w_ih0, w_hh0, b_ih0, b_hh0,
                                        w_ih1, w_hh1, b_ih1, b_hh1,
                                        fc_w, fc_b, out);
}